// round 12
// baseline (speedup 1.0000x reference)
#include <cuda_runtime.h>
#include <math.h>
#include <stdint.h>

// ---------------------------------------------------------------------------
// HashEncoderHyFluid, R10: R9 (469us: lane-pair gathers + 4-level batched
// coalesced stores) with TWO levels fused per loop iteration. 16 independent
// gathers per iteration (vs 8) let ptxas hoist level-B loads over level-A
// accumulation -> fewer L1tex idle cycles (measured 93.1% -> target ~97%).
// Work and wavefront counts are unchanged; this is pure scheduling slack.
// ---------------------------------------------------------------------------

struct Level {
    float    rf0, rf1, rf2, rf3;   // res as float32
    unsigned s1, s2, s3;           // dense strides
    unsigned mask;                 // size-1 (hashed pow2)
    unsigned size;
    int      offset;               // float offset into hash_table
    int      mode;                 // 0 dense, 1 hash+mask, 2 hash+mod
};
struct KConfig { Level lv[16]; };

#define HPRIME1 2654435761u
#define HPRIME2 805459861u
#define HPRIME3 3674653429u

// one query-half (this lane's x-corner), one level: returns post-shfl result
__device__ __forceinline__ void enc_level(const float4& X, const Level& L,
                                          const float* __restrict__ tab,
                                          unsigned xb, unsigned amask,
                                          float& out0, float& out1)
{
    float px = X.x * L.rf0, py = X.y * L.rf1, pz = X.z * L.rf2, pt = X.w * L.rf3;
    float gx = floorf(px),  gy = floorf(py),  gz = floorf(pz),  gt = floorf(pt);
    float fx = px - gx,     fy = py - gy,     fz = pz - gz,     ft = pt - gt;
    unsigned cx = (unsigned)(int)gx, cy = (unsigned)(int)gy;
    unsigned cz = (unsigned)(int)gz, ct = (unsigned)(int)gt;

    float wxs = xb ? fx : (1.f - fx);
    float wy0 = 1.f - fy, wz0 = 1.f - fz, wt0 = 1.f - ft;
    float wzt[4];
    wzt[0] = wz0 * wt0;  wzt[1] = fz * wt0;  wzt[2] = wz0 * ft;  wzt[3] = fz * ft;
    float wj[8];
    #pragma unroll
    for (int k = 0; k < 4; ++k) { wj[k] = wy0 * wzt[k]; wj[4 + k] = fy * wzt[k]; }

    unsigned bx = cx + xb;
    unsigned idx[8];
    if (L.mode == 0) {
        unsigned base0 = bx + cy * L.s1 + cz * L.s2 + ct * L.s3;
        idx[0] = base0;
        idx[1] = base0 + L.s2;
        idx[2] = base0 + L.s3;
        idx[3] = base0 + L.s2 + L.s3;
        #pragma unroll
        for (int k = 0; k < 4; ++k) idx[4 + k] = idx[k] + L.s1;
    } else if (L.mode == 1) {
        unsigned hy = cy * HPRIME1, hz = cz * HPRIME2, ht = ct * HPRIME3;
        unsigned msk = L.mask;
        unsigned rzt[4] = { hz ^ ht, (hz + HPRIME2) ^ ht,
                            hz ^ (ht + HPRIME3), (hz + HPRIME2) ^ (ht + HPRIME3) };
        #pragma unroll
        for (int k = 0; k < 4; ++k) {
            idx[k]     = (bx ^ hy             ^ rzt[k]) & msk;
            idx[4 + k] = (bx ^ (hy + HPRIME1) ^ rzt[k]) & msk;
        }
    } else {
        unsigned hy = cy * HPRIME1, hz = cz * HPRIME2, ht = ct * HPRIME3;
        unsigned sz = L.size;
        unsigned rzt[4] = { hz ^ ht, (hz + HPRIME2) ^ ht,
                            hz ^ (ht + HPRIME3), (hz + HPRIME2) ^ (ht + HPRIME3) };
        #pragma unroll
        for (int k = 0; k < 4; ++k) {
            idx[k]     = (bx ^ hy             ^ rzt[k]) % sz;
            idx[4 + k] = (bx ^ (hy + HPRIME1) ^ rzt[k]) % sz;
        }
    }

    const float2* t2 = reinterpret_cast<const float2*>(tab) + (L.offset >> 1);
    float a0 = 0.f, a1 = 0.f;
    #pragma unroll
    for (int k = 0; k < 8; ++k) {
        float2 f = __ldg(t2 + idx[k]);    // pair lanes hit the same 128B line
        a0 += wj[k] * f.x;
        a1 += wj[k] * f.y;
    }
    a0 *= wxs;
    a1 *= wxs;
    a0 += __shfl_xor_sync(amask, a0, 1);
    a1 += __shfl_xor_sync(amask, a1, 1);
    out0 = a0; out1 = a1;
}

__global__ __launch_bounds__(256)
void hashenc_kernel(const float4* __restrict__ xyzt,
                    const float*  __restrict__ tab,
                    float*        __restrict__ out,
                    KConfig cfg, int n)
{
    int tid = blockIdx.x * 256 + threadIdx.x;
    int q = tid >> 1;              // two lanes per query
    if (q >= n) return;
    const unsigned xb = (unsigned)(tid & 1);
    const unsigned amask = __activemask();   // pair lanes exit together

    float4 X = __ldg(&xyzt[q]);
    float4* orow = reinterpret_cast<float4*>(out + (size_t)q * 32);

    // 4-level group g: even lane buffers levels 4g,4g+1 -> slot 2g;
    // odd lane buffers levels 4g+2,4g+3 -> slot 2g+1. Same 128B row.
    #pragma unroll 1
    for (int g = 0; g < 4; ++g) {
        float e0, e1, f0, f1, g0, g1, h0, h1;
        enc_level(X, cfg.lv[4 * g],     tab, xb, amask, e0, e1);
        enc_level(X, cfg.lv[4 * g + 1], tab, xb, amask, f0, f1);
        enc_level(X, cfg.lv[4 * g + 2], tab, xb, amask, g0, g1);
        enc_level(X, cfg.lv[4 * g + 3], tab, xb, amask, h0, h1);
        float4 v = xb ? make_float4(g0, g1, h0, h1)
                      : make_float4(e0, e1, f0, f1);
        orow[(g << 1) + xb] = v;   // both lanes -> same row, 1 coalesced wf
    }
}

// ---------------------------------------------------------------------------
// Host-side config: mirrors reference build_config() op-for-op in float64.
// ---------------------------------------------------------------------------
static KConfig build_cfg_host()
{
    const double minr[4] = {16.0, 16.0, 16.0, 16.0};
    const double maxr[4] = {256.0, 256.0, 256.0, 128.0};
    const long long MAXP = 524288; // 2^19

    double b[4];
    for (int d = 0; d < 4; ++d)
        b[d] = exp((log(maxr[d]) - log(minr[d])) / 15.0);

    KConfig cfg;
    long long total = 0;
    for (int s = 0; s < 16; ++s) {
        long long res[4];
        for (int d = 0; d < 4; ++d)
            res[d] = (long long)ceil(minr[d] * pow(b[d], (double)s));
        long long raw = (res[0] + 1) * (res[1] + 1) * (res[2] + 1) * (res[3] + 1);
        long long p = (raw % 8 == 0) ? raw : ((raw + 7) / 8) * 8;
        if (p > MAXP) p = MAXP;
        int dense = (raw <= p) ? 1 : 0;

        Level& L = cfg.lv[s];
        L.rf0 = (float)res[0]; L.rf1 = (float)res[1];
        L.rf2 = (float)res[2]; L.rf3 = (float)res[3];
        L.s1 = (unsigned)(res[0] + 1);
        L.s2 = (unsigned)((res[0] + 1) * (res[1] + 1));
        L.s3 = (unsigned)((res[0] + 1) * (res[1] + 1) * (res[2] + 1));
        L.size = (unsigned)p;
        L.mask = (unsigned)(p - 1);
        L.offset = (int)total;
        if (dense)                      L.mode = 0;
        else if ((p & (p - 1)) == 0)    L.mode = 1;
        else                            L.mode = 2;
        total += p * 2;  // F = 2
    }
    return cfg;
}

extern "C" void kernel_launch(void* const* d_in, const int* in_sizes, int n_in,
                              void* d_out, int out_size)
{
    static KConfig cfg = build_cfg_host();

    const float4* xyzt = (const float4*)d_in[0];
    const float*  tab  = (const float*)d_in[1];
    float*        out  = (float*)d_out;

    int n = in_sizes[0] / 4;
    long long threads = 2LL * n;
    int blocks = (int)((threads + 255) / 256);
    hashenc_kernel<<<blocks, 256>>>(xyzt, tab, out, cfg, n);
}

// round 13
// speedup vs baseline: 1.6296x; 1.6296x over previous
#include <cuda_runtime.h>
#include <math.h>
#include <stdint.h>

// ---------------------------------------------------------------------------
// HashEncoderHyFluid, R11: R9 scheme (lane-pair cooperative gathers + 4-level
// batched coalesced stores; 469us) with TWO levels fused per call and
// __launch_bounds__(256,1) so ptxas allocates registers for the doubled live
// set instead of spilling to local memory (R10 failure mode: 39 regs + LDL/STL
// through L1tex -> 764us). 16 independent gathers per fused body feed the
// L1tex pipe across accumulation bubbles.
// ---------------------------------------------------------------------------

struct Level {
    float    rf0, rf1, rf2, rf3;   // res as float32
    unsigned s1, s2, s3;           // dense strides
    unsigned mask;                 // size-1 (hashed pow2)
    unsigned size;
    int      offset;               // float offset into hash_table
    int      mode;                 // 0 dense, 1 hash+mask, 2 hash+mod
};
struct KConfig { Level lv[16]; };

#define HPRIME1 2654435761u
#define HPRIME2 805459861u
#define HPRIME3 3674653429u

// compute this lane's 8 gather indices + 8 weights + x-weight for one level
__device__ __forceinline__ void level_setup(const float4& X, const Level& L,
                                            unsigned xb,
                                            unsigned idx[8], float wj[8],
                                            float& wxs)
{
    float px = X.x * L.rf0, py = X.y * L.rf1, pz = X.z * L.rf2, pt = X.w * L.rf3;
    float gx = floorf(px),  gy = floorf(py),  gz = floorf(pz),  gt = floorf(pt);
    float fx = px - gx,     fy = py - gy,     fz = pz - gz,     ft = pt - gt;
    unsigned cx = (unsigned)(int)gx, cy = (unsigned)(int)gy;
    unsigned cz = (unsigned)(int)gz, ct = (unsigned)(int)gt;

    wxs = xb ? fx : (1.f - fx);
    float wy0 = 1.f - fy, wz0 = 1.f - fz, wt0 = 1.f - ft;
    float wzt[4];
    wzt[0] = wz0 * wt0;  wzt[1] = fz * wt0;  wzt[2] = wz0 * ft;  wzt[3] = fz * ft;
    #pragma unroll
    for (int k = 0; k < 4; ++k) { wj[k] = wy0 * wzt[k]; wj[4 + k] = fy * wzt[k]; }

    unsigned bx = cx + xb;
    if (L.mode == 0) {
        unsigned base0 = bx + cy * L.s1 + cz * L.s2 + ct * L.s3;
        idx[0] = base0;
        idx[1] = base0 + L.s2;
        idx[2] = base0 + L.s3;
        idx[3] = base0 + L.s2 + L.s3;
        #pragma unroll
        for (int k = 0; k < 4; ++k) idx[4 + k] = idx[k] + L.s1;
    } else if (L.mode == 1) {
        unsigned hy = cy * HPRIME1, hz = cz * HPRIME2, ht = ct * HPRIME3;
        unsigned msk = L.mask;
        unsigned rzt[4] = { hz ^ ht, (hz + HPRIME2) ^ ht,
                            hz ^ (ht + HPRIME3), (hz + HPRIME2) ^ (ht + HPRIME3) };
        #pragma unroll
        for (int k = 0; k < 4; ++k) {
            idx[k]     = (bx ^ hy             ^ rzt[k]) & msk;
            idx[4 + k] = (bx ^ (hy + HPRIME1) ^ rzt[k]) & msk;
        }
    } else {
        unsigned hy = cy * HPRIME1, hz = cz * HPRIME2, ht = ct * HPRIME3;
        unsigned sz = L.size;
        unsigned rzt[4] = { hz ^ ht, (hz + HPRIME2) ^ ht,
                            hz ^ (ht + HPRIME3), (hz + HPRIME2) ^ (ht + HPRIME3) };
        #pragma unroll
        for (int k = 0; k < 4; ++k) {
            idx[k]     = (bx ^ hy             ^ rzt[k]) % sz;
            idx[4 + k] = (bx ^ (hy + HPRIME1) ^ rzt[k]) % sz;
        }
    }
}

// two levels fused: 16 independent gathers issued together
__device__ __forceinline__ void enc2(const float4& X,
                                     const Level& LA, const Level& LB,
                                     const float* __restrict__ tab,
                                     unsigned xb, unsigned amask,
                                     float& ra0, float& ra1,
                                     float& rb0, float& rb1)
{
    unsigned ia[8], ib[8];
    float    wa[8], wb[8];
    float    wxa, wxb;
    level_setup(X, LA, xb, ia, wa, wxa);
    level_setup(X, LB, xb, ib, wb, wxb);

    const float2* ta = reinterpret_cast<const float2*>(tab) + (LA.offset >> 1);
    const float2* tb = reinterpret_cast<const float2*>(tab) + (LB.offset >> 1);

    float2 fa[8], fb[8];
    #pragma unroll
    for (int k = 0; k < 8; ++k) fa[k] = __ldg(ta + ia[k]);
    #pragma unroll
    for (int k = 0; k < 8; ++k) fb[k] = __ldg(tb + ib[k]);

    float a0 = 0.f, a1 = 0.f, b0 = 0.f, b1 = 0.f;
    #pragma unroll
    for (int k = 0; k < 8; ++k) {
        a0 += wa[k] * fa[k].x;  a1 += wa[k] * fa[k].y;
        b0 += wb[k] * fb[k].x;  b1 += wb[k] * fb[k].y;
    }
    a0 *= wxa;  a1 *= wxa;  b0 *= wxb;  b1 *= wxb;
    a0 += __shfl_xor_sync(amask, a0, 1);
    a1 += __shfl_xor_sync(amask, a1, 1);
    b0 += __shfl_xor_sync(amask, b0, 1);
    b1 += __shfl_xor_sync(amask, b1, 1);
    ra0 = a0; ra1 = a1; rb0 = b0; rb1 = b1;
}

__global__ __launch_bounds__(256, 1)
void hashenc_kernel(const float4* __restrict__ xyzt,
                    const float*  __restrict__ tab,
                    float*        __restrict__ out,
                    KConfig cfg, int n)
{
    int tid = blockIdx.x * 256 + threadIdx.x;
    int q = tid >> 1;              // two lanes per query
    if (q >= n) return;
    const unsigned xb = (unsigned)(tid & 1);
    const unsigned amask = __activemask();   // pair lanes exit together

    float4 X = __ldg(&xyzt[q]);
    float4* orow = reinterpret_cast<float4*>(out + (size_t)q * 32);

    // 4-level group g: even lane buffers levels 4g,4g+1 -> slot 2g;
    // odd lane buffers levels 4g+2,4g+3 -> slot 2g+1. Same 128B row.
    #pragma unroll 1
    for (int g = 0; g < 4; ++g) {
        float e0, e1, f0, f1, g0, g1, h0, h1;
        enc2(X, cfg.lv[4 * g],     cfg.lv[4 * g + 1], tab, xb, amask, e0, e1, f0, f1);
        enc2(X, cfg.lv[4 * g + 2], cfg.lv[4 * g + 3], tab, xb, amask, g0, g1, h0, h1);
        float4 v = xb ? make_float4(g0, g1, h0, h1)
                      : make_float4(e0, e1, f0, f1);
        orow[(g << 1) + xb] = v;   // both lanes -> same 128B row, 1 coalesced wf
    }
}

// ---------------------------------------------------------------------------
// Host-side config: mirrors reference build_config() op-for-op in float64.
// ---------------------------------------------------------------------------
static KConfig build_cfg_host()
{
    const double minr[4] = {16.0, 16.0, 16.0, 16.0};
    const double maxr[4] = {256.0, 256.0, 256.0, 128.0};
    const long long MAXP = 524288; // 2^19

    double b[4];
    for (int d = 0; d < 4; ++d)
        b[d] = exp((log(maxr[d]) - log(minr[d])) / 15.0);

    KConfig cfg;
    long long total = 0;
    for (int s = 0; s < 16; ++s) {
        long long res[4];
        for (int d = 0; d < 4; ++d)
            res[d] = (long long)ceil(minr[d] * pow(b[d], (double)s));
        long long raw = (res[0] + 1) * (res[1] + 1) * (res[2] + 1) * (res[3] + 1);
        long long p = (raw % 8 == 0) ? raw : ((raw + 7) / 8) * 8;
        if (p > MAXP) p = MAXP;
        int dense = (raw <= p) ? 1 : 0;

        Level& L = cfg.lv[s];
        L.rf0 = (float)res[0]; L.rf1 = (float)res[1];
        L.rf2 = (float)res[2]; L.rf3 = (float)res[3];
        L.s1 = (unsigned)(res[0] + 1);
        L.s2 = (unsigned)((res[0] + 1) * (res[1] + 1));
        L.s3 = (unsigned)((res[0] + 1) * (res[1] + 1) * (res[2] + 1));
        L.size = (unsigned)p;
        L.mask = (unsigned)(p - 1);
        L.offset = (int)total;
        if (dense)                      L.mode = 0;
        else if ((p & (p - 1)) == 0)    L.mode = 1;
        else                            L.mode = 2;
        total += p * 2;  // F = 2
    }
    return cfg;
}

extern "C" void kernel_launch(void* const* d_in, const int* in_sizes, int n_in,
                              void* d_out, int out_size)
{
    static KConfig cfg = build_cfg_host();

    const float4* xyzt = (const float4*)d_in[0];
    const float*  tab  = (const float*)d_in[1];
    float*        out  = (float*)d_out;

    int n = in_sizes[0] / 4;
    long long threads = 2LL * n;
    int blocks = (int)((threads + 255) / 256);
    hashenc_kernel<<<blocks, 256>>>(xyzt, tab, out, cfg, n);
}